// round 1
// baseline (speedup 1.0000x reference)
#include <cuda_runtime.h>

// Prediction_65189013618796
// prob: [B=64, 2N=2048] float32.  start = prob[:, :N], end = prob[:, N:].
// band: 0 <= j - i <= 15 (token_span).
// All inputs are non-negative (uniform[0,1)), so:
//   start_position[b,i] = start[b,i] * max(end[b, i .. min(i+15, N-1)])
//   end_position[b,j]   = end[b,j]   * max(start[b, max(j-15,0) .. j])
// Output: float32 [2, B, N] -> start_position then end_position, each B*N.

#define NB 64
#define NN 1024
#define SPAN 15

__global__ __launch_bounds__(1024, 1)
void banded_span_kernel(const float* __restrict__ prob, float* __restrict__ out) {
    __shared__ float s[2 * NN];  // [0..NN): start, [NN..2NN): end

    const int b = blockIdx.x;
    const int t = threadIdx.x;           // 0..1023

    // Stage the whole row (2048 floats) with one float2 per thread.
    const float2* row2 = reinterpret_cast<const float2*>(prob + (size_t)b * 2 * NN);
    reinterpret_cast<float2*>(s)[t] = row2[t];
    __syncthreads();

    const float* __restrict__ s_start = s;
    const float* __restrict__ s_end   = s + NN;

    // Forward window max over end: j = t .. min(t+SPAN, N-1)
    float me = s_end[t];
    const int hi = (t + SPAN < NN - 1) ? (t + SPAN) : (NN - 1);
    #pragma unroll
    for (int k = 1; k <= SPAN; ++k) {
        int j = t + k;
        if (j <= hi) me = fmaxf(me, s_end[j]);
    }
    out[(size_t)b * NN + t] = s_start[t] * me;

    // Backward window max over start: i = max(t-SPAN, 0) .. t
    float ms = s_start[t];
    const int lo = (t - SPAN > 0) ? (t - SPAN) : 0;
    #pragma unroll
    for (int k = 1; k <= SPAN; ++k) {
        int i = t - k;
        if (i >= lo) ms = fmaxf(ms, s_start[i]);
    }
    out[(size_t)NB * NN + (size_t)b * NN + t] = s_end[t] * ms;
}

extern "C" void kernel_launch(void* const* d_in, const int* in_sizes, int n_in,
                              void* d_out, int out_size) {
    const float* prob = (const float*)d_in[0];
    float* out = (float*)d_out;
    banded_span_kernel<<<NB, 1024>>>(prob, out);
}